// round 1
// baseline (speedup 1.0000x reference)
#include <cuda_runtime.h>

#define BB 8
#define CC 512
#define DD 64
#define NN 16384
#define PARAM 10.0f
#define EPS 1e-6f

// Scratch (device globals: allocation-free)
__device__ float g_Q[BB * DD * NN];      // phi(Q)  [b, m, n]
__device__ float g_K[BB * DD * NN];      // phi(K)  [b, m, n]
__device__ float g_Ksum[BB * DD];        // sum_n phi(K)
__device__ float g_KX[BB * DD * CC];     // phi(K) @ x^T
__device__ float g_KV[BB * DD * CC];     // KX @ Wv^T + bv * Ksum
__device__ float g_rnorm[BB * NN];       // 1 / (phiQ . (Ksum+eps))

__device__ __forceinline__ float fmap(float t) {
    // 10*relu(t) + exp(10*min(t,0)):  t>0 -> 10t+1 ; t<=0 -> exp(10t)
    return t > 0.f ? fmaf(PARAM, t, 1.f) : __expf(PARAM * t);
}

// ---------------------------------------------------------------------------
// Kernel 0: zero accumulators
// ---------------------------------------------------------------------------
__global__ void k_zero() {
    int i = blockIdx.x * blockDim.x + threadIdx.x;
    if (i < BB * DD * CC) g_KX[i] = 0.f;
    if (i < BB * DD)      g_Ksum[i] = 0.f;
}

// ---------------------------------------------------------------------------
// Kernel 1: fused Q/K projection. [128rows x 512] @ [512 x N] per batch.
// Rows 0..63 = Q (Wq,bq), rows 64..127 = K (Wk,bk). Applies feature map,
// accumulates Ksum via warp-reduced atomics.
// Block: 256 thr (16x16), tile 128m x 128n, micro 8x8.
// ---------------------------------------------------------------------------
__global__ void k_qk(const float* __restrict__ x,
                     const float* __restrict__ Wq, const float* __restrict__ bq,
                     const float* __restrict__ Wk, const float* __restrict__ bk) {
    __shared__ float As[32][129];  // [k][m], padded
    __shared__ float Bs[32][128];  // [k][n]
    const int b  = blockIdx.y;
    const int n0 = blockIdx.x * 128;
    const int tid = threadIdx.x;
    const int tx = tid & 15, ty = tid >> 4;
    const float* xb = x + (size_t)b * CC * NN;

    float acc[8][8] = {};
    for (int kc = 0; kc < CC; kc += 32) {
        {
            int c = tid & 31;
            #pragma unroll
            for (int m = tid >> 5; m < 128; m += 8)
                As[c][m] = (m < 64) ? Wq[m * CC + kc + c] : Wk[(m - 64) * CC + kc + c];
        }
        {
            int n = tid & 127;
            #pragma unroll
            for (int c = tid >> 7; c < 32; c += 2)
                Bs[c][n] = xb[(size_t)(kc + c) * NN + n0 + n];
        }
        __syncthreads();
        #pragma unroll
        for (int k = 0; k < 32; k++) {
            float a[8], bv[8];
            #pragma unroll
            for (int i = 0; i < 8; i++) a[i] = As[k][ty + 16 * i];
            #pragma unroll
            for (int j = 0; j < 8; j++) bv[j] = Bs[k][tx + 16 * j];
            #pragma unroll
            for (int i = 0; i < 8; i++)
                #pragma unroll
                for (int j = 0; j < 8; j++)
                    acc[i][j] = fmaf(a[i], bv[j], acc[i][j]);
        }
        __syncthreads();
    }

    #pragma unroll
    for (int i = 0; i < 8; i++) {
        const int m = ty + 16 * i;
        const float bias = (m < 64) ? bq[m] : bk[m - 64];
        float* dst = (m < 64) ? &g_Q[((size_t)b * DD + m) * NN]
                              : &g_K[((size_t)b * DD + (m - 64)) * NN];
        float rsum = 0.f;
        #pragma unroll
        for (int j = 0; j < 8; j++) {
            float v = fmap(acc[i][j] + bias);
            dst[n0 + tx + 16 * j] = v;
            rsum += v;
        }
        if (m >= 64) {
            #pragma unroll
            for (int off = 8; off; off >>= 1)
                rsum += __shfl_down_sync(0xffffffffu, rsum, off, 16);
            if (tx == 0) atomicAdd(&g_Ksum[b * DD + m - 64], rsum);
        }
    }
}

// ---------------------------------------------------------------------------
// Kernel 2: per-pixel reciprocal denominator. 1/(phiQ[:,n] . (Ksum+eps))
// ---------------------------------------------------------------------------
__global__ void k_denom() {
    const int b = blockIdx.y;
    const int n = blockIdx.x * 128 + threadIdx.x;
    float acc = 0.f;
    #pragma unroll
    for (int m = 0; m < DD; m++)
        acc = fmaf(g_Q[((size_t)b * DD + m) * NN + n], g_Ksum[b * DD + m] + EPS, acc);
    g_rnorm[b * NN + n] = 1.f / acc;
}

// ---------------------------------------------------------------------------
// Kernel 3: KX[b,m,c] = sum_n phiK[b,m,n] * x[b,c,n]   (split-K over n, atomics)
// Block: 256 thr (16x16), tile 64m x 64c, micro 4x4, each block reduces 512 n.
// ---------------------------------------------------------------------------
__global__ void k_kx(const float* __restrict__ x) {
    __shared__ float Ks[32][65];  // [n][m]
    __shared__ float Xs[32][65];  // [n][c]
    const int n0 = blockIdx.x * 512;
    const int c0 = blockIdx.y * 64;
    const int b  = blockIdx.z;
    const int tid = threadIdx.x;
    const int tx = tid & 15, ty = tid >> 4;

    float acc[4][4] = {};
    for (int kn = 0; kn < 512; kn += 32) {
        {
            int n = tid & 31;
            #pragma unroll
            for (int m = tid >> 5; m < 64; m += 8)
                Ks[n][m] = g_K[((size_t)b * DD + m) * NN + n0 + kn + n];
            #pragma unroll
            for (int c = tid >> 5; c < 64; c += 8)
                Xs[n][c] = x[((size_t)b * CC + c0 + c) * NN + n0 + kn + n];
        }
        __syncthreads();
        #pragma unroll
        for (int k = 0; k < 32; k++) {
            float a[4], bv[4];
            #pragma unroll
            for (int i = 0; i < 4; i++) a[i] = Ks[k][ty + 16 * i];
            #pragma unroll
            for (int j = 0; j < 4; j++) bv[j] = Xs[k][tx + 16 * j];
            #pragma unroll
            for (int i = 0; i < 4; i++)
                #pragma unroll
                for (int j = 0; j < 4; j++)
                    acc[i][j] = fmaf(a[i], bv[j], acc[i][j]);
        }
        __syncthreads();
    }
    #pragma unroll
    for (int i = 0; i < 4; i++)
        #pragma unroll
        for (int j = 0; j < 4; j++)
            atomicAdd(&g_KX[((size_t)b * DD + ty + 16 * i) * CC + c0 + tx + 16 * j],
                      acc[i][j]);
}

// ---------------------------------------------------------------------------
// Kernel 4: KV[b,m,c] = sum_{c'} KX[b,m,c'] * Wv[c,c'] + bv[c]*Ksum[b,m]
// ---------------------------------------------------------------------------
__global__ void k_kv(const float* __restrict__ Wv, const float* __restrict__ bv) {
    __shared__ float As[32][65];  // [c'][m]
    __shared__ float Ws[32][65];  // [c'][c]
    const int c0 = blockIdx.x * 64;
    const int b  = blockIdx.y;
    const int tid = threadIdx.x;
    const int tx = tid & 15, ty = tid >> 4;

    float acc[4][4] = {};
    for (int kc = 0; kc < CC; kc += 32) {
        {
            int cc = tid & 31;
            #pragma unroll
            for (int m = tid >> 5; m < 64; m += 8)
                As[cc][m] = g_KX[((size_t)b * DD + m) * CC + kc + cc];
            #pragma unroll
            for (int c = tid >> 5; c < 64; c += 8)
                Ws[cc][c] = Wv[(size_t)(c0 + c) * CC + kc + cc];
        }
        __syncthreads();
        #pragma unroll
        for (int k = 0; k < 32; k++) {
            float a[4], w[4];
            #pragma unroll
            for (int i = 0; i < 4; i++) a[i] = As[k][ty + 16 * i];
            #pragma unroll
            for (int j = 0; j < 4; j++) w[j] = Ws[k][tx + 16 * j];
            #pragma unroll
            for (int i = 0; i < 4; i++)
                #pragma unroll
                for (int j = 0; j < 4; j++)
                    acc[i][j] = fmaf(a[i], w[j], acc[i][j]);
        }
        __syncthreads();
    }
    #pragma unroll
    for (int i = 0; i < 4; i++) {
        int m = ty + 16 * i;
        float ks = g_Ksum[b * DD + m];
        #pragma unroll
        for (int j = 0; j < 4; j++) {
            int c = c0 + tx + 16 * j;
            g_KV[((size_t)b * DD + m) * CC + c] = fmaf(bv[c], ks, acc[i][j]);
        }
    }
}

// ---------------------------------------------------------------------------
// Kernel 5: out[b,c,n] = x[b,c,n] + gamma * rnorm[n] * sum_m phiQ[m,n]*KV[m,c]
// Block: 256 thr (16x16), tile 64n x 128c, micro 4n x 8c. Static smem = 48KB.
// ---------------------------------------------------------------------------
__global__ void k_out(const float* __restrict__ x, const float* __restrict__ gamma,
                      float* __restrict__ out) {
    __shared__ float Qs[64][64];    // [m][n]
    __shared__ float KVs[64][128];  // [m][c]
    const int n0 = blockIdx.x * 64;
    const int c0 = blockIdx.y * 128;
    const int b  = blockIdx.z;
    const int tid = threadIdx.x;
    const int tx = tid & 15, ty = tid >> 4;

    {
        int n = tid & 63;
        #pragma unroll
        for (int m = tid >> 6; m < 64; m += 4)
            Qs[m][n] = g_Q[((size_t)b * DD + m) * NN + n0 + n];
    }
    {
        int c = tid & 127;
        #pragma unroll
        for (int m = tid >> 7; m < 64; m += 2)
            KVs[m][c] = g_KV[((size_t)b * DD + m) * CC + c0 + c];
    }
    __syncthreads();

    float acc[8][4] = {};  // [c micro][n micro]
    #pragma unroll
    for (int k = 0; k < 64; k++) {
        float a[4], bv[8];
        #pragma unroll
        for (int jn = 0; jn < 4; jn++) a[jn] = Qs[k][tx + 16 * jn];
        #pragma unroll
        for (int jc = 0; jc < 8; jc++) bv[jc] = KVs[k][ty + 16 * jc];
        #pragma unroll
        for (int jc = 0; jc < 8; jc++)
            #pragma unroll
            for (int jn = 0; jn < 4; jn++)
                acc[jc][jn] = fmaf(bv[jc], a[jn], acc[jc][jn]);
    }

    const float gm = gamma[0];
    #pragma unroll
    for (int jn = 0; jn < 4; jn++) {
        const int n = n0 + tx + 16 * jn;
        const float rn = g_rnorm[b * NN + n] * gm;
        #pragma unroll
        for (int jc = 0; jc < 8; jc++) {
            const int c = c0 + ty + 16 * jc;
            const size_t gi = ((size_t)b * CC + c) * NN + n;
            out[gi] = fmaf(acc[jc][jn], rn, x[gi]);
        }
    }
}

// ---------------------------------------------------------------------------
extern "C" void kernel_launch(void* const* d_in, const int* in_sizes, int n_in,
                              void* d_out, int out_size) {
    const float* x     = (const float*)d_in[0];
    const float* Wq    = (const float*)d_in[1];
    const float* bq    = (const float*)d_in[2];
    const float* Wk    = (const float*)d_in[3];
    const float* bk    = (const float*)d_in[4];
    const float* Wv    = (const float*)d_in[5];
    const float* bv    = (const float*)d_in[6];
    const float* gamma = (const float*)d_in[7];
    float* out = (float*)d_out;

    k_zero <<<512, 512>>>();
    k_qk   <<<dim3(NN / 128, BB), 256>>>(x, Wq, bq, Wk, bk);
    k_denom<<<dim3(NN / 128, BB), 128>>>();
    k_kx   <<<dim3(32, CC / 64, BB), 256>>>(x);
    k_kv   <<<dim3(CC / 64, BB), 256>>>(Wv, bv);
    k_out  <<<dim3(NN / 64, CC / 128, BB), 256>>>(x, gamma, out);
}

// round 2
// speedup vs baseline: 1.0961x; 1.0961x over previous
#include <cuda_runtime.h>

#define BB 8
#define CC 512
#define DD 64
#define NN 16384
#define PARAM 10.0f
#define EPS 1e-6f
#define NSPLIT 16

// Scratch (device globals: allocation-free)
__device__ float g_Q[BB * DD * NN];      // phi(Q)  [b, m, n]
__device__ float g_K[BB * DD * NN];      // phi(K)  [b, m, n]
__device__ float g_Ksum[BB * DD];        // sum_n phi(K)
__device__ float g_KX[BB * DD * CC];     // phi(K) @ x^T
__device__ float g_KV[BB * DD * CC];     // KX @ Wv^T + bv * Ksum

__device__ __forceinline__ float fmap(float t) {
    // 10*relu(t) + exp(10*min(t,0)):  t>0 -> 10t+1 ; t<=0 -> exp(10t)
    return t > 0.f ? fmaf(PARAM, t, 1.f) : __expf(PARAM * t);
}

// ---------------------------------------------------------------------------
// Kernel 0: zero accumulators
// ---------------------------------------------------------------------------
__global__ void k_zero() {
    int i = blockIdx.x * blockDim.x + threadIdx.x;
    if (i < BB * DD * CC) g_KX[i] = 0.f;
    if (i < BB * DD)      g_Ksum[i] = 0.f;
}

// ---------------------------------------------------------------------------
// Kernel 1: fused Q/K projection. [128rows x 512] @ [512 x N] per batch.
// Rows 0..63 = Q (Wq,bq), rows 64..127 = K (Wk,bk). Applies feature map,
// accumulates Ksum via warp-reduced atomics.
// 256 thr, tile 128m x 128n, micro 8x8, float4 LDS/LDG/STG, kchunk=16.
// ---------------------------------------------------------------------------
__global__ __launch_bounds__(256) void k_qk(
        const float* __restrict__ x,
        const float* __restrict__ Wq, const float* __restrict__ bq,
        const float* __restrict__ Wk, const float* __restrict__ bk) {
    __shared__ float As[16][128];  // [k][m]
    __shared__ float Bs[16][128];  // [k][n]
    const int b  = blockIdx.y;
    const int n0 = blockIdx.x * 128;
    const int tid = threadIdx.x;
    const int tx = tid & 15, ty = tid >> 4;
    const float* xb = x + (size_t)b * CC * NN;

    float acc[8][8] = {};
    for (int kc = 0; kc < CC; kc += 16) {
        // As: 128 rows of W (Q|K), cols kc..kc+15, stored [k][m]
        #pragma unroll
        for (int i = 0; i < 2; i++) {
            int idx = tid + i * 256;
            int m  = idx >> 2;            // 0..127
            int c4 = (idx & 3) * 4;       // 0,4,8,12
            const float* Wrow = (m < 64) ? (Wq + m * CC) : (Wk + (m - 64) * CC);
            float4 w = *(const float4*)(Wrow + kc + c4);
            As[c4 + 0][m] = w.x; As[c4 + 1][m] = w.y;
            As[c4 + 2][m] = w.z; As[c4 + 3][m] = w.w;
        }
        // Bs: x tile [k][n], direct float4
        #pragma unroll
        for (int i = 0; i < 2; i++) {
            int idx = tid + i * 256;
            int c  = idx >> 5;            // 0..15
            int n4 = (idx & 31) * 4;      // 0..124
            *(float4*)&Bs[c][n4] =
                *(const float4*)(xb + (size_t)(kc + c) * NN + n0 + n4);
        }
        __syncthreads();
        #pragma unroll
        for (int k = 0; k < 16; k++) {
            float4 a0 = *(float4*)&As[k][ty * 8];
            float4 a1 = *(float4*)&As[k][ty * 8 + 4];
            float4 b0 = *(float4*)&Bs[k][tx * 8];
            float4 b1 = *(float4*)&Bs[k][tx * 8 + 4];
            float a[8] = {a0.x, a0.y, a0.z, a0.w, a1.x, a1.y, a1.z, a1.w};
            float bv[8] = {b0.x, b0.y, b0.z, b0.w, b1.x, b1.y, b1.z, b1.w};
            #pragma unroll
            for (int i = 0; i < 8; i++)
                #pragma unroll
                for (int j = 0; j < 8; j++)
                    acc[i][j] = fmaf(a[i], bv[j], acc[i][j]);
        }
        __syncthreads();
    }

    // Epilogue: ty<8 -> Q rows (m=ty*8+i), ty>=8 -> K rows.
    #pragma unroll
    for (int i = 0; i < 8; i++) {
        const int m = ty * 8 + i;
        if (ty < 8) {
            const float bias = bq[m];
            float v[8];
            #pragma unroll
            for (int j = 0; j < 8; j++) v[j] = fmap(acc[i][j] + bias);
            float* dst = g_Q + ((size_t)b * DD + m) * NN + n0 + tx * 8;
            *(float4*)(dst)     = make_float4(v[0], v[1], v[2], v[3]);
            *(float4*)(dst + 4) = make_float4(v[4], v[5], v[6], v[7]);
        } else {
            const int mm = m - 64;
            const float bias = bk[mm];
            float v[8], rsum = 0.f;
            #pragma unroll
            for (int j = 0; j < 8; j++) { v[j] = fmap(acc[i][j] + bias); rsum += v[j]; }
            float* dst = g_K + ((size_t)b * DD + mm) * NN + n0 + tx * 8;
            *(float4*)(dst)     = make_float4(v[0], v[1], v[2], v[3]);
            *(float4*)(dst + 4) = make_float4(v[4], v[5], v[6], v[7]);
            #pragma unroll
            for (int off = 8; off; off >>= 1)
                rsum += __shfl_down_sync(0xffffffffu, rsum, off, 16);
            if (tx == 0) atomicAdd(&g_Ksum[b * DD + mm], rsum);
        }
    }
}

// ---------------------------------------------------------------------------
// Kernel 2: KX[b,m,c] = sum_n phiK[b,m,n] * x[b,c,n]   (split-K over n)
// 256 thr, tile 64m x 128c, micro 4m x 8c, kchunk=32, float4 everywhere.
// ---------------------------------------------------------------------------
__global__ __launch_bounds__(256) void k_kx(const float* __restrict__ x) {
    __shared__ float Ks[32][68];   // [n][m], padded
    __shared__ float Xs[32][132];  // [n][c], padded
    const int n_base = blockIdx.x * (NN / NSPLIT);   // 1024-wide split
    const int c0 = blockIdx.y * 128;
    const int b  = blockIdx.z;
    const int tid = threadIdx.x;
    const int tx = tid & 15, ty = tid >> 4;

    float acc[4][8] = {};
    for (int kn = 0; kn < NN / NSPLIT; kn += 32) {
        const size_t nb = n_base + kn;
        // Ks: [m][n] gmem -> [n][m] smem (float4 LDG, scalar STS)
        #pragma unroll
        for (int i = 0; i < 2; i++) {
            int idx = tid + i * 256;
            int m   = idx >> 3;           // 0..63
            int nn4 = (idx & 7) * 4;      // 0..28
            float4 kv = *(const float4*)(g_K + ((size_t)b * DD + m) * NN + nb + nn4);
            Ks[nn4 + 0][m] = kv.x; Ks[nn4 + 1][m] = kv.y;
            Ks[nn4 + 2][m] = kv.z; Ks[nn4 + 3][m] = kv.w;
        }
        // Xs: [c][n] gmem -> [n][c] smem
        #pragma unroll
        for (int i = 0; i < 4; i++) {
            int idx = tid + i * 256;
            int c   = idx >> 3;           // 0..127
            int nn4 = (idx & 7) * 4;
            float4 xv = *(const float4*)(x + ((size_t)(b * CC + c0 + c)) * NN + nb + nn4);
            Xs[nn4 + 0][c] = xv.x; Xs[nn4 + 1][c] = xv.y;
            Xs[nn4 + 2][c] = xv.z; Xs[nn4 + 3][c] = xv.w;
        }
        __syncthreads();
        #pragma unroll
        for (int k = 0; k < 32; k++) {
            float4 a  = *(float4*)&Ks[k][ty * 4];
            float4 b0 = *(float4*)&Xs[k][tx * 8];
            float4 b1 = *(float4*)&Xs[k][tx * 8 + 4];
            float av[4] = {a.x, a.y, a.z, a.w};
            float bv[8] = {b0.x, b0.y, b0.z, b0.w, b1.x, b1.y, b1.z, b1.w};
            #pragma unroll
            for (int i = 0; i < 4; i++)
                #pragma unroll
                for (int j = 0; j < 8; j++)
                    acc[i][j] = fmaf(av[i], bv[j], acc[i][j]);
        }
        __syncthreads();
    }
    #pragma unroll
    for (int i = 0; i < 4; i++)
        #pragma unroll
        for (int j = 0; j < 8; j++)
            atomicAdd(&g_KX[((size_t)b * DD + ty * 4 + i) * CC + c0 + tx * 8 + j],
                      acc[i][j]);
}

// ---------------------------------------------------------------------------
// Kernel 3: KV[b,m,c] = sum_{c'} KX[b,m,c'] * Wv[c,c'] + bv[c]*Ksum[b,m]
// Tiny (268 MF). 256 thr, tile 64x64, micro 4x4.
// ---------------------------------------------------------------------------
__global__ void k_kv(const float* __restrict__ Wv, const float* __restrict__ bv) {
    __shared__ float As[32][65];  // [c'][m]
    __shared__ float Ws[32][65];  // [c'][c]
    const int c0 = blockIdx.x * 64;
    const int b  = blockIdx.y;
    const int tid = threadIdx.x;
    const int tx = tid & 15, ty = tid >> 4;

    float acc[4][4] = {};
    for (int kc = 0; kc < CC; kc += 32) {
        {
            int cc = tid & 31;
            #pragma unroll
            for (int m = tid >> 5; m < 64; m += 8)
                As[cc][m] = g_KX[((size_t)b * DD + m) * CC + kc + cc];
            #pragma unroll
            for (int c = tid >> 5; c < 64; c += 8)
                Ws[cc][c] = Wv[(size_t)(c0 + c) * CC + kc + cc];
        }
        __syncthreads();
        #pragma unroll
        for (int k = 0; k < 32; k++) {
            float a[4], w[4];
            #pragma unroll
            for (int i = 0; i < 4; i++) a[i] = As[k][ty + 16 * i];
            #pragma unroll
            for (int j = 0; j < 4; j++) w[j] = Ws[k][tx + 16 * j];
            #pragma unroll
            for (int i = 0; i < 4; i++)
                #pragma unroll
                for (int j = 0; j < 4; j++)
                    acc[i][j] = fmaf(a[i], w[j], acc[i][j]);
        }
        __syncthreads();
    }
    #pragma unroll
    for (int i = 0; i < 4; i++) {
        int m = ty + 16 * i;
        float ks = g_Ksum[b * DD + m];
        #pragma unroll
        for (int j = 0; j < 4; j++) {
            int c = c0 + tx + 16 * j;
            g_KV[((size_t)b * DD + m) * CC + c] = fmaf(bv[c], ks, acc[i][j]);
        }
    }
}

// ---------------------------------------------------------------------------
// Kernel 4: out[b,c,n] = x + gamma * rnorm[n] * sum_m phiQ[m,n]*KV[m,c]
// Fuses the denominator: den[n] = sum_m phiQ[m,n]*(Ksum[m]+eps).
// 256 thr, tile 128n x 128c, micro 8x8, kchunk=32, float4 everywhere.
// ---------------------------------------------------------------------------
__global__ __launch_bounds__(256) void k_out(
        const float* __restrict__ x, const float* __restrict__ gamma,
        float* __restrict__ out) {
    __shared__ float Qs[32][128];    // [m][n]
    __shared__ float KVs[32][128];   // [m][c]
    __shared__ float ksum_s[DD];
    const int c0 = blockIdx.x * 128;   // c fastest: c-tiles of same n share Q in L2
    const int n0 = blockIdx.y * 128;
    const int b  = blockIdx.z;
    const int tid = threadIdx.x;
    const int tx = tid & 15, ty = tid >> 4;

    if (tid < DD) ksum_s[tid] = g_Ksum[b * DD + tid] + EPS;

    float acc[8][8] = {};   // [c][n]
    float den[8] = {};
    for (int m0 = 0; m0 < DD; m0 += 32) {
        __syncthreads();   // also orders ksum_s write before first use
        #pragma unroll
        for (int i = 0; i < 4; i++) {
            int idx = tid + i * 256;
            int m  = idx >> 5;
            int n4 = (idx & 31) * 4;
            *(float4*)&Qs[m][n4] =
                *(const float4*)(g_Q + ((size_t)b * DD + m0 + m) * NN + n0 + n4);
        }
        #pragma unroll
        for (int i = 0; i < 4; i++) {
            int idx = tid + i * 256;
            int m  = idx >> 5;
            int c4 = (idx & 31) * 4;
            *(float4*)&KVs[m][c4] =
                *(const float4*)(g_KV + ((size_t)b * DD + m0 + m) * CC + c0 + c4);
        }
        __syncthreads();
        #pragma unroll
        for (int k = 0; k < 32; k++) {
            float4 a0 = *(float4*)&Qs[k][tx * 8];
            float4 a1 = *(float4*)&Qs[k][tx * 8 + 4];
            float4 b0 = *(float4*)&KVs[k][ty * 8];
            float4 b1 = *(float4*)&KVs[k][ty * 8 + 4];
            float a[8]  = {a0.x, a0.y, a0.z, a0.w, a1.x, a1.y, a1.z, a1.w};
            float bf[8] = {b0.x, b0.y, b0.z, b0.w, b1.x, b1.y, b1.z, b1.w};
            const float ks = ksum_s[m0 + k];
            #pragma unroll
            for (int j = 0; j < 8; j++) den[j] = fmaf(a[j], ks, den[j]);
            #pragma unroll
            for (int i = 0; i < 8; i++)
                #pragma unroll
                for (int j = 0; j < 8; j++)
                    acc[i][j] = fmaf(bf[i], a[j], acc[i][j]);
        }
    }

    const float gm = gamma[0];
    float rn[8];
    #pragma unroll
    for (int j = 0; j < 8; j++) rn[j] = gm / den[j];

    #pragma unroll
    for (int i = 0; i < 8; i++) {
        const int c = c0 + ty * 8 + i;
        const size_t base = ((size_t)b * CC + c) * NN + n0 + tx * 8;
        float4 x0 = *(const float4*)(x + base);
        float4 x1 = *(const float4*)(x + base + 4);
        float4 o0, o1;
        o0.x = fmaf(acc[i][0], rn[0], x0.x);
        o0.y = fmaf(acc[i][1], rn[1], x0.y);
        o0.z = fmaf(acc[i][2], rn[2], x0.z);
        o0.w = fmaf(acc[i][3], rn[3], x0.w);
        o1.x = fmaf(acc[i][4], rn[4], x1.x);
        o1.y = fmaf(acc[i][5], rn[5], x1.y);
        o1.z = fmaf(acc[i][6], rn[6], x1.z);
        o1.w = fmaf(acc[i][7], rn[7], x1.w);
        *(float4*)(out + base)     = o0;
        *(float4*)(out + base + 4) = o1;
    }
}

// ---------------------------------------------------------------------------
extern "C" void kernel_launch(void* const* d_in, const int* in_sizes, int n_in,
                              void* d_out, int out_size) {
    const float* x     = (const float*)d_in[0];
    const float* Wq    = (const float*)d_in[1];
    const float* bq    = (const float*)d_in[2];
    const float* Wk    = (const float*)d_in[3];
    const float* bk    = (const float*)d_in[4];
    const float* Wv    = (const float*)d_in[5];
    const float* bv    = (const float*)d_in[6];
    const float* gamma = (const float*)d_in[7];
    float* out = (float*)d_out;

    k_zero<<<512, 512>>>();
    k_qk  <<<dim3(NN / 128, BB), 256>>>(x, Wq, bq, Wk, bk);
    k_kx  <<<dim3(NSPLIT, CC / 128, BB), 256>>>(x);
    k_kv  <<<dim3(CC / 64, BB), 256>>>(Wv, bv);
    k_out <<<dim3(CC / 128, NN / 128, BB), 256>>>(x, gamma, out);
}